// round 5
// baseline (speedup 1.0000x reference)
#include <cuda_runtime.h>
#include <cuda_bf16.h>

// Fixed problem shapes
#define B_  4
#define T_  16
#define O_  32
#define H_  181
#define W_  360
#define BT_ (B_ * T_)          // 64 images
#define P_  (BT_ * O_)         // 2048 points
#define HW_ (H_ * W_)          // 65160 px

#define GAUSS_C (-0.5f / (2.5f * 2.5f + 1e-8f))
#define EPS_    1e-8f

// Windowed tables: 48 slots, valid window at slots [8..40] (33 grid indices),
// slot s <-> grid index start + s - 8. Slots outside hold 0 (zero padding for
// branchless clamped reads).
#define WSLOT 48

__device__ float        g_latw[P_ * WSLOT];
__device__ float        g_lonw[P_ * WSLOT];
__device__ int          g_latstart[P_];
__device__ int          g_lonstart[P_];
__device__ unsigned int g_maxbits[BT_];

// ---------------------------------------------------------------------------
// Kernel A: windowed exp tables. One block per image, 256 threads,
// 32 points x 96 slots = 3072 items -> 12 per thread. One wave.
// ---------------------------------------------------------------------------
__global__ __launch_bounds__(256)
void traj_tables_kernel(const float* __restrict__ traj,
                        const float* __restrict__ lat,
                        const float* __restrict__ lon)
{
    const int img = blockIdx.x;
    const int tid = threadIdx.x;
    if (tid == 0) g_maxbits[img] = 0u;

    for (int i = tid; i < O_ * 2 * WSLOT; i += 256) {
        const int pl = i / (2 * WSLOT);
        const int s  = i % (2 * WSLOT);
        const int p  = img * O_ + pl;
        const float lat_t = traj[p * 2 + 0];
        const float lon_t = traj[p * 2 + 1];
        // lat grid: -90 + i (step 1.0); lon grid: -180 + i*(360/359)
        const int lat_start = (int)floorf(lat_t + 90.0f) - 16;
        const int lon_start = (int)floorf((lon_t + 180.0f) * (359.0f / 360.0f)) - 16;
        if (s == 0) {
            g_latstart[p] = lat_start;
            g_lonstart[p] = lon_start;
        }
        if (s < WSLOT) {
            int gi = lat_start + s - 8;
            float v = 0.0f;
            if (s >= 8 && s <= 40 && gi >= 0 && gi < H_) {
                float d = lat[gi] - lat_t;
                v = __expf(GAUSS_C * d * d);
            }
            g_latw[p * WSLOT + s] = v;
        } else {
            int t = s - WSLOT;
            int gi = lon_start + t - 8;
            float v = 0.0f;
            if (t >= 8 && t <= 40 && gi >= 0 && gi < W_) {
                float d = lon[gi] - lon_t;
                v = __expf(GAUSS_C * d * d);
            }
            g_lonw[p * WSLOT + t] = v;
        }
    }
}

// ---------------------------------------------------------------------------
// Shared patch geometry: block = 128 thr, block patch 32 rows x 128 cols,
// warp patch 16x64, thread tile 4x8. grid = (3, 6, 64).
// ---------------------------------------------------------------------------

// Kernel B1: per-image max only (no heat stores). Early-exit on empty patches.
__global__ __launch_bounds__(128)
void traj_max_kernel()
{
    __shared__ float slatw[O_ * WSLOT];
    __shared__ float slonw[O_ * WSLOT];
    __shared__ int   slats[O_];
    __shared__ int   slons[O_];
    __shared__ unsigned smask;
    __shared__ float sred[4];

    const int img = blockIdx.z;
    const int tid = threadIdx.x;

    if (tid < O_) {
        slats[tid] = g_latstart[img * O_ + tid];
        slons[tid] = g_lonstart[img * O_ + tid];
    }
    __syncthreads();

    const int BR0 = blockIdx.y * 32,  BR1 = BR0 + 31;
    const int BC0 = blockIdx.x * 128, BC1 = BC0 + 127;
    if (tid < 32) {
        const int ls = slats[tid], cs = slons[tid];
        const bool act = !(BR1 < ls || BR0 > ls + 32 || BC1 < cs || BC0 > cs + 32);
        const unsigned m = __ballot_sync(0xFFFFFFFFu, act);
        if (tid == 0) smask = m;
    }
    __syncthreads();
    const unsigned mask = smask;
    if (mask == 0u) return;

    {
        const float* glat = g_latw + img * (O_ * WSLOT);
        const float* glon = g_lonw + img * (O_ * WSLOT);
        for (int i = tid; i < O_ * WSLOT; i += 128) {
            slatw[i] = glat[i];
            slonw[i] = glon[i];
        }
    }
    __syncthreads();

    const int w  = tid >> 5, l = tid & 31;
    const int wr = w >> 1, wc = w & 1;
    const int rg = l >> 3, cg = l & 7;
    const int R0 = BR0 + wr * 16 + rg * 4;
    const int C0 = BC0 + wc * 64 + cg * 8;

    float acc[4][8];
    #pragma unroll
    for (int j = 0; j < 4; j++)
        #pragma unroll
        for (int k = 0; k < 8; k++) acc[j][k] = 0.0f;

    for (unsigned m = mask; m; m &= (m - 1)) {
        const int o = __ffs(m) - 1;
        const int ls = slats[o], cs = slons[o];
        if (R0 + 3 < ls || R0 > ls + 32 || C0 + 7 < cs || C0 > cs + 32) continue;

        float a[4], v[8];
        #pragma unroll
        for (int j = 0; j < 4; j++) {
            int idx = min(max(R0 + j - ls + 8, 0), WSLOT - 1);
            a[j] = slatw[o * WSLOT + idx];
        }
        #pragma unroll
        for (int k = 0; k < 8; k++) {
            int idx = min(max(C0 + k - cs + 8, 0), WSLOT - 1);
            v[k] = slonw[o * WSLOT + idx];
        }
        #pragma unroll
        for (int j = 0; j < 4; j++)
            #pragma unroll
            for (int k = 0; k < 8; k++)
                acc[j][k] = fmaf(a[j], v[k], acc[j][k]);
    }

    // Max only over valid pixels
    float lmax = 0.0f;
    const bool colok = (C0 < W_);
    #pragma unroll
    for (int j = 0; j < 4; j++) {
        if (colok && (R0 + j) < H_) {
            #pragma unroll
            for (int k = 0; k < 8; k++) lmax = fmaxf(lmax, acc[j][k]);
        }
    }
    #pragma unroll
    for (int off = 16; off > 0; off >>= 1)
        lmax = fmaxf(lmax, __shfl_xor_sync(0xFFFFFFFFu, lmax, off));
    if (l == 0) sred[w] = lmax;
    __syncthreads();
    if (tid == 0) {
        float mx = fmaxf(fmaxf(sred[0], sred[1]), fmaxf(sred[2], sred[3]));
        atomicMax(reinterpret_cast<int*>(&g_maxbits[img]), __float_as_int(mx));
    }
}

// Kernel B2: recompute heat and write normalized output directly.
__global__ __launch_bounds__(128)
void traj_write_kernel(float* __restrict__ out)
{
    __shared__ float slatw[O_ * WSLOT];
    __shared__ float slonw[O_ * WSLOT];
    __shared__ int   slats[O_];
    __shared__ int   slons[O_];
    __shared__ unsigned smask;

    const int img = blockIdx.z;
    const int tid = threadIdx.x;

    if (tid < O_) {
        slats[tid] = g_latstart[img * O_ + tid];
        slons[tid] = g_lonstart[img * O_ + tid];
    }
    __syncthreads();

    const int BR0 = blockIdx.y * 32,  BR1 = BR0 + 31;
    const int BC0 = blockIdx.x * 128, BC1 = BC0 + 127;
    if (tid < 32) {
        const int ls = slats[tid], cs = slons[tid];
        const bool act = !(BR1 < ls || BR0 > ls + 32 || BC1 < cs || BC0 > cs + 32);
        const unsigned m = __ballot_sync(0xFFFFFFFFu, act);
        if (tid == 0) smask = m;
    }
    __syncthreads();
    const unsigned mask = smask;

    const int w  = tid >> 5, l = tid & 31;
    const int wr = w >> 1, wc = w & 1;
    const int rg = l >> 3, cg = l & 7;
    const int R0 = BR0 + wr * 16 + rg * 4;
    const int C0 = BC0 + wc * 64 + cg * 8;
    float* oimg = out + img * HW_;
    const bool colok = (C0 < W_);   // C0 multiple of 8; 360 % 8 == 0

    if (mask == 0u) {
        // Empty patch: just write zeros (out is poisoned, must be written).
        const float4 z = make_float4(0.f, 0.f, 0.f, 0.f);
        #pragma unroll
        for (int j = 0; j < 4; j++) {
            const int r = R0 + j;
            if (colok && r < H_) {
                *reinterpret_cast<float4*>(&oimg[r * W_ + C0])     = z;
                *reinterpret_cast<float4*>(&oimg[r * W_ + C0 + 4]) = z;
            }
        }
        return;
    }

    {
        const float* glat = g_latw + img * (O_ * WSLOT);
        const float* glon = g_lonw + img * (O_ * WSLOT);
        for (int i = tid; i < O_ * WSLOT; i += 128) {
            slatw[i] = glat[i];
            slonw[i] = glon[i];
        }
    }
    __syncthreads();

    const float mx  = __int_as_float((int)g_maxbits[img]);
    const float inv = 1.0f / (mx + EPS_);

    float acc[4][8];
    #pragma unroll
    for (int j = 0; j < 4; j++)
        #pragma unroll
        for (int k = 0; k < 8; k++) acc[j][k] = 0.0f;

    for (unsigned m = mask; m; m &= (m - 1)) {
        const int o = __ffs(m) - 1;
        const int ls = slats[o], cs = slons[o];
        if (R0 + 3 < ls || R0 > ls + 32 || C0 + 7 < cs || C0 > cs + 32) continue;

        float a[4], v[8];
        #pragma unroll
        for (int j = 0; j < 4; j++) {
            int idx = min(max(R0 + j - ls + 8, 0), WSLOT - 1);
            a[j] = slatw[o * WSLOT + idx];
        }
        #pragma unroll
        for (int k = 0; k < 8; k++) {
            int idx = min(max(C0 + k - cs + 8, 0), WSLOT - 1);
            v[k] = slonw[o * WSLOT + idx];
        }
        #pragma unroll
        for (int j = 0; j < 4; j++)
            #pragma unroll
            for (int k = 0; k < 8; k++)
                acc[j][k] = fmaf(a[j], v[k], acc[j][k]);
    }

    #pragma unroll
    for (int j = 0; j < 4; j++) {
        const int r = R0 + j;
        if (colok && r < H_) {
            float4 v0 = make_float4(acc[j][0] * inv, acc[j][1] * inv,
                                    acc[j][2] * inv, acc[j][3] * inv);
            float4 v1 = make_float4(acc[j][4] * inv, acc[j][5] * inv,
                                    acc[j][6] * inv, acc[j][7] * inv);
            *reinterpret_cast<float4*>(&oimg[r * W_ + C0])     = v0;
            *reinterpret_cast<float4*>(&oimg[r * W_ + C0 + 4]) = v1;
        }
    }
}

// ---------------------------------------------------------------------------
extern "C" void kernel_launch(void* const* d_in, const int* in_sizes, int n_in,
                              void* d_out, int out_size)
{
    const float* traj = (const float*)d_in[0];  // (4,16,32,2)
    const float* lat  = (const float*)d_in[1];  // (181,)
    const float* lon  = (const float*)d_in[2];  // (360,)
    float* out = (float*)d_out;                 // (64,181,360) f32

    traj_tables_kernel<<<BT_, 256>>>(traj, lat, lon);

    dim3 grid_b(3, 6, BT_);   // 3 col-patches x 6 row-patches x 64 images
    traj_max_kernel<<<grid_b, 128>>>();
    traj_write_kernel<<<grid_b, 128>>>(out);
}

// round 6
// speedup vs baseline: 1.1931x; 1.1931x over previous
#include <cuda_runtime.h>
#include <cuda_bf16.h>

// Fixed problem shapes
#define B_  4
#define T_  16
#define O_  32
#define H_  181
#define W_  360
#define BT_ (B_ * T_)          // 64 images
#define HW_ (H_ * W_)          // 65160 px

#define GAUSS_C (-0.5f / (2.5f * 2.5f + 1e-8f))
#define EPS_    1e-8f

// Windowed tables: 48 slots, valid at slots [8..40] (33 grid indices),
// slot s <-> grid index start + s - 8. Out-of-window slots hold 0 so
// clamped reads are branchless.
#define WSLOT 48

#define NTHREADS 512
#define NGROUPS  4            // 128-thread groups
#define NPATCH   18           // 6 row patches (32) x 3 col patches (128)

// ---------------------------------------------------------------------------
// Single fused kernel: one block per image.
//   Phase 1: windowed exp tables in SMEM.
//   Phase 2: per-image max (patch gather, empty-patch skip, smem reduce).
//   Phase 3: recompute + write normalized output.
// ---------------------------------------------------------------------------
__global__ __launch_bounds__(NTHREADS)
void traj_fused_kernel(const float* __restrict__ traj,
                       const float* __restrict__ lat,
                       const float* __restrict__ lon,
                       float* __restrict__ out)
{
    __shared__ float straj[O_ * 2];
    __shared__ float slatw[O_ * WSLOT];   // 6 KB
    __shared__ float slonw[O_ * WSLOT];   // 6 KB
    __shared__ int   slats[O_];
    __shared__ int   slons[O_];
    __shared__ float sred[NTHREADS / 32];
    __shared__ float sinv;

    const int img = blockIdx.x;
    const int tid = threadIdx.x;

    // ---- Phase 1: tables ----
    if (tid < O_ * 2) straj[tid] = traj[img * O_ * 2 + tid];
    __syncthreads();

    if (tid < O_) {
        const float lat_t = straj[tid * 2 + 0];
        const float lon_t = straj[tid * 2 + 1];
        // lat grid: -90 + i (step 1.0); lon grid: -180 + i*(360/359)
        slats[tid] = (int)floorf(lat_t + 90.0f) - 16;
        slons[tid] = (int)floorf((lon_t + 180.0f) * (359.0f / 360.0f)) - 16;
    }
    __syncthreads();

    for (int i = tid; i < O_ * 2 * WSLOT; i += NTHREADS) {
        const int pl = i / (2 * WSLOT);
        const int s  = i % (2 * WSLOT);
        if (s < WSLOT) {
            int gi = slats[pl] + s - 8;
            float v = 0.0f;
            if (s >= 8 && s <= 40 && gi >= 0 && gi < H_) {
                float d = lat[gi] - straj[pl * 2 + 0];
                v = __expf(GAUSS_C * d * d);
            }
            slatw[pl * WSLOT + s] = v;
        } else {
            int t  = s - WSLOT;
            int gi = slons[pl] + t - 8;
            float v = 0.0f;
            if (t >= 8 && t <= 40 && gi >= 0 && gi < W_) {
                float d = lon[gi] - straj[pl * 2 + 1];
                v = __expf(GAUSS_C * d * d);
            }
            slonw[pl * WSLOT + t] = v;
        }
    }
    __syncthreads();

    // ---- Patch geometry: group of 128 threads owns a 32x128 patch ----
    const int g    = tid >> 7;          // group 0..3
    const int gtid = tid & 127;
    const int w    = gtid >> 5, l = gtid & 31;
    const int wr   = w >> 1,  wc = w & 1;   // 2x2 warps: 16 rows x 64 cols each
    const int rg   = l >> 3,  cg = l & 7;   // thread tile 4 rows x 8 cols
    const int rOff = wr * 16 + rg * 4;
    const int cOff = wc * 64 + cg * 8;

    // ---- Phase 2: per-image max ----
    float lmax = 0.0f;
    for (int p = g; p < NPATCH; p += NGROUPS) {
        const int BR0 = (p / 3) * 32;
        const int BC0 = (p % 3) * 128;

        // Warp-uniform active-point mask (each lane tests one point)
        const int tls = slats[l], tcs = slons[l];
        const bool act = !(BR0 + 31 < tls || BR0 > tls + 32 ||
                           BC0 + 127 < tcs || BC0 > tcs + 32);
        const unsigned mask = __ballot_sync(0xFFFFFFFFu, act);
        if (mask == 0u) continue;

        const int R0 = BR0 + rOff;
        const int C0 = BC0 + cOff;

        float acc[4][8];
        #pragma unroll
        for (int j = 0; j < 4; j++)
            #pragma unroll
            for (int k = 0; k < 8; k++) acc[j][k] = 0.0f;

        for (unsigned m = mask; m; m &= (m - 1)) {
            const int o = __ffs(m) - 1;
            const int ls = slats[o], cs = slons[o];
            if (R0 + 3 < ls || R0 > ls + 32 || C0 + 7 < cs || C0 > cs + 32)
                continue;
            float a[4], v[8];
            #pragma unroll
            for (int j = 0; j < 4; j++) {
                int idx = min(max(R0 + j - ls + 8, 0), WSLOT - 1);
                a[j] = slatw[o * WSLOT + idx];
            }
            #pragma unroll
            for (int k = 0; k < 8; k++) {
                int idx = min(max(C0 + k - cs + 8, 0), WSLOT - 1);
                v[k] = slonw[o * WSLOT + idx];
            }
            #pragma unroll
            for (int j = 0; j < 4; j++)
                #pragma unroll
                for (int k = 0; k < 8; k++)
                    acc[j][k] = fmaf(a[j], v[k], acc[j][k]);
        }

        const bool colok = (C0 < W_);   // C0 multiple of 8; W_ % 8 == 0
        #pragma unroll
        for (int j = 0; j < 4; j++) {
            if (colok && (R0 + j) < H_) {
                #pragma unroll
                for (int k = 0; k < 8; k++) lmax = fmaxf(lmax, acc[j][k]);
            }
        }
    }

    // Block max reduction
    #pragma unroll
    for (int off = 16; off > 0; off >>= 1)
        lmax = fmaxf(lmax, __shfl_xor_sync(0xFFFFFFFFu, lmax, off));
    if (l == 0) sred[tid >> 5] = lmax;
    __syncthreads();
    if (tid == 0) {
        float mx = 0.0f;
        #pragma unroll
        for (int i = 0; i < NTHREADS / 32; i++) mx = fmaxf(mx, sred[i]);
        sinv = 1.0f / (mx + EPS_);
    }
    __syncthreads();
    const float inv = sinv;

    // ---- Phase 3: recompute + normalized write ----
    float* oimg = out + img * HW_;
    for (int p = g; p < NPATCH; p += NGROUPS) {
        const int BR0 = (p / 3) * 32;
        const int BC0 = (p % 3) * 128;
        const int R0 = BR0 + rOff;
        const int C0 = BC0 + cOff;
        const bool colok = (C0 < W_);

        const int tls = slats[l], tcs = slons[l];
        const bool act = !(BR0 + 31 < tls || BR0 > tls + 32 ||
                           BC0 + 127 < tcs || BC0 > tcs + 32);
        const unsigned mask = __ballot_sync(0xFFFFFFFFu, act);

        if (mask == 0u) {
            const float4 z = make_float4(0.f, 0.f, 0.f, 0.f);
            #pragma unroll
            for (int j = 0; j < 4; j++) {
                const int r = R0 + j;
                if (colok && r < H_) {
                    *reinterpret_cast<float4*>(&oimg[r * W_ + C0])     = z;
                    *reinterpret_cast<float4*>(&oimg[r * W_ + C0 + 4]) = z;
                }
            }
            continue;
        }

        float acc[4][8];
        #pragma unroll
        for (int j = 0; j < 4; j++)
            #pragma unroll
            for (int k = 0; k < 8; k++) acc[j][k] = 0.0f;

        for (unsigned m = mask; m; m &= (m - 1)) {
            const int o = __ffs(m) - 1;
            const int ls = slats[o], cs = slons[o];
            if (R0 + 3 < ls || R0 > ls + 32 || C0 + 7 < cs || C0 > cs + 32)
                continue;
            float a[4], v[8];
            #pragma unroll
            for (int j = 0; j < 4; j++) {
                int idx = min(max(R0 + j - ls + 8, 0), WSLOT - 1);
                a[j] = slatw[o * WSLOT + idx];
            }
            #pragma unroll
            for (int k = 0; k < 8; k++) {
                int idx = min(max(C0 + k - cs + 8, 0), WSLOT - 1);
                v[k] = slonw[o * WSLOT + idx];
            }
            #pragma unroll
            for (int j = 0; j < 4; j++)
                #pragma unroll
                for (int k = 0; k < 8; k++)
                    acc[j][k] = fmaf(a[j], v[k], acc[j][k]);
        }

        #pragma unroll
        for (int j = 0; j < 4; j++) {
            const int r = R0 + j;
            if (colok && r < H_) {
                float4 v0 = make_float4(acc[j][0] * inv, acc[j][1] * inv,
                                        acc[j][2] * inv, acc[j][3] * inv);
                float4 v1 = make_float4(acc[j][4] * inv, acc[j][5] * inv,
                                        acc[j][6] * inv, acc[j][7] * inv);
                *reinterpret_cast<float4*>(&oimg[r * W_ + C0])     = v0;
                *reinterpret_cast<float4*>(&oimg[r * W_ + C0 + 4]) = v1;
            }
        }
    }
}

// ---------------------------------------------------------------------------
extern "C" void kernel_launch(void* const* d_in, const int* in_sizes, int n_in,
                              void* d_out, int out_size)
{
    const float* traj = (const float*)d_in[0];  // (4,16,32,2)
    const float* lat  = (const float*)d_in[1];  // (181,)
    const float* lon  = (const float*)d_in[2];  // (360,)
    float* out = (float*)d_out;                 // (64,181,360) f32

    traj_fused_kernel<<<BT_, NTHREADS>>>(traj, lat, lon, out);
}

// round 8
// speedup vs baseline: 1.5038x; 1.2605x over previous
#include <cuda_runtime.h>
#include <cuda_bf16.h>
#include <cooperative_groups.h>

namespace cgr = cooperative_groups;

// Fixed problem shapes
#define B_  4
#define T_  16
#define O_  32
#define H_  181
#define W_  360
#define BT_ (B_ * T_)          // 64 images
#define HW_ (H_ * W_)          // 65160 px

#define GAUSS_C (-0.5f / (2.5f * 2.5f + 1e-8f))
#define EPS_    1e-8f

// Windowed tables: 48 slots, valid at slots [8..40] (33 grid indices),
// slot s <-> grid index start + s - 8. Out-of-window slots hold 0 so
// clamped reads are branchless.
#define WSLOT 48

#define NTHREADS 384           // 3 groups of 128
#define CLUSTER  2             // 2 CTAs per image, 9 patches each

// ---------------------------------------------------------------------------
// One cluster (2 CTAs) per image. Each CTA:
//   Phase 1: windowed exp tables in SMEM (full image tables, cheap).
//   Phase 2: gather its 9 patches (32x128 each) into REGISTERS, local max.
//   Max exchange via DSMEM + cluster.sync.
//   Phase 3: scale registers and store (no recompute).
// ---------------------------------------------------------------------------
__global__ __launch_bounds__(NTHREADS, 1) __cluster_dims__(CLUSTER, 1, 1)
void traj_fused_kernel(const float* __restrict__ traj,
                       const float* __restrict__ lat,
                       const float* __restrict__ lon,
                       float* __restrict__ out)
{
    __shared__ float straj[O_ * 2];
    __shared__ float slatw[O_ * WSLOT];   // 6 KB
    __shared__ float slonw[O_ * WSLOT];   // 6 KB
    __shared__ int   slats[O_];
    __shared__ int   slons[O_];
    __shared__ float sred[NTHREADS / 32];
    __shared__ float smax_own;
    __shared__ float smax_peer;

    cgr::cluster_group cluster = cgr::this_cluster();
    const unsigned rank = cluster.block_rank();     // 0 or 1
    const int img = blockIdx.x >> 1;
    const int tid = threadIdx.x;

    // ---- Phase 1: tables ----
    if (tid < O_ * 2) straj[tid] = traj[img * O_ * 2 + tid];
    __syncthreads();

    if (tid < O_) {
        const float lat_t = straj[tid * 2 + 0];
        const float lon_t = straj[tid * 2 + 1];
        // lat grid: -90 + i (step 1.0); lon grid: -180 + i*(360/359)
        slats[tid] = (int)floorf(lat_t + 90.0f) - 16;
        slons[tid] = (int)floorf((lon_t + 180.0f) * (359.0f / 360.0f)) - 16;
    }
    __syncthreads();

    for (int i = tid; i < O_ * 2 * WSLOT; i += NTHREADS) {
        const int pl = i / (2 * WSLOT);
        const int s  = i % (2 * WSLOT);
        if (s < WSLOT) {
            int gi = slats[pl] + s - 8;
            float v = 0.0f;
            if (s >= 8 && s <= 40 && gi >= 0 && gi < H_) {
                float d = lat[gi] - straj[pl * 2 + 0];
                v = __expf(GAUSS_C * d * d);
            }
            slatw[pl * WSLOT + s] = v;
        } else {
            int t  = s - WSLOT;
            int gi = slons[pl] + t - 8;
            float v = 0.0f;
            if (t >= 8 && t <= 40 && gi >= 0 && gi < W_) {
                float d = lon[gi] - straj[pl * 2 + 1];
                v = __expf(GAUSS_C * d * d);
            }
            slonw[pl * WSLOT + t] = v;
        }
    }
    __syncthreads();

    // ---- Geometry: group of 128 threads owns patch-row (rank*3+g), all 3 col patches ----
    const int g    = tid / 128;           // 0..2
    const int gtid = tid % 128;
    const int w    = gtid >> 5, l = gtid & 31;
    const int wr   = w >> 1,  wc = w & 1;     // 2x2 warps: 16 rows x 64 cols
    const int rg   = l >> 3,  cgi = l & 7;    // thread tile 4 rows x 8 cols
    const int rOff = wr * 16 + rg * 4;
    const int cOff = wc * 64 + cgi * 8;

    const int BR0 = ((int)rank * 3 + g) * 32;
    const int R0  = BR0 + rOff;
    const int tls = slats[l], tcs = slons[l];   // this lane's test point

    // ---- Phase 2: gather into registers + local max ----
    float acc[3][4][8];
    #pragma unroll
    for (int pc = 0; pc < 3; pc++)
        #pragma unroll
        for (int j = 0; j < 4; j++)
            #pragma unroll
            for (int k = 0; k < 8; k++) acc[pc][j][k] = 0.0f;

    float lmax = 0.0f;
    #pragma unroll
    for (int pc = 0; pc < 3; pc++) {
        const int BC0 = pc * 128;
        const int C0  = BC0 + cOff;

        const bool act = !(BR0 + 31 < tls || BR0 > tls + 32 ||
                           BC0 + 127 < tcs || BC0 > tcs + 32);
        unsigned mask = __ballot_sync(0xFFFFFFFFu, act);

        for (; mask; mask &= (mask - 1)) {
            const int o = __ffs(mask) - 1;
            const int ls = slats[o], cs = slons[o];
            if (R0 + 3 < ls || R0 > ls + 32 || C0 + 7 < cs || C0 > cs + 32)
                continue;
            float a[4], v[8];
            #pragma unroll
            for (int j = 0; j < 4; j++) {
                int idx = min(max(R0 + j - ls + 8, 0), WSLOT - 1);
                a[j] = slatw[o * WSLOT + idx];
            }
            #pragma unroll
            for (int k = 0; k < 8; k++) {
                int idx = min(max(C0 + k - cs + 8, 0), WSLOT - 1);
                v[k] = slonw[o * WSLOT + idx];
            }
            #pragma unroll
            for (int j = 0; j < 4; j++)
                #pragma unroll
                for (int k = 0; k < 8; k++)
                    acc[pc][j][k] = fmaf(a[j], v[k], acc[pc][j][k]);
        }

        const bool colok = (C0 < W_);     // C0 multiple of 8; W_ % 8 == 0
        #pragma unroll
        for (int j = 0; j < 4; j++) {
            if (colok && (R0 + j) < H_) {
                #pragma unroll
                for (int k = 0; k < 8; k++)
                    lmax = fmaxf(lmax, acc[pc][j][k]);
            }
        }
    }

    // ---- Block max reduce, then cross-CTA exchange via DSMEM ----
    #pragma unroll
    for (int off = 16; off > 0; off >>= 1)
        lmax = fmaxf(lmax, __shfl_xor_sync(0xFFFFFFFFu, lmax, off));
    if (l == 0) sred[tid >> 5] = lmax;
    __syncthreads();
    if (tid == 0) {
        float bmax = 0.0f;
        #pragma unroll
        for (int i = 0; i < NTHREADS / 32; i++) bmax = fmaxf(bmax, sred[i]);
        smax_own = bmax;
        float* peer = (float*)cluster.map_shared_rank(&smax_peer, rank ^ 1u);
        *peer = bmax;
    }
    cluster.sync();
    const float inv = 1.0f / (fmaxf(smax_own, smax_peer) + EPS_);

    // ---- Phase 3: scale registers and store ----
    float* oimg = out + img * HW_;
    #pragma unroll
    for (int pc = 0; pc < 3; pc++) {
        const int C0 = pc * 128 + cOff;
        const bool colok = (C0 < W_);
        #pragma unroll
        for (int j = 0; j < 4; j++) {
            const int r = R0 + j;
            if (colok && r < H_) {
                float4 v0 = make_float4(acc[pc][j][0] * inv, acc[pc][j][1] * inv,
                                        acc[pc][j][2] * inv, acc[pc][j][3] * inv);
                float4 v1 = make_float4(acc[pc][j][4] * inv, acc[pc][j][5] * inv,
                                        acc[pc][j][6] * inv, acc[pc][j][7] * inv);
                *reinterpret_cast<float4*>(&oimg[r * W_ + C0])     = v0;
                *reinterpret_cast<float4*>(&oimg[r * W_ + C0 + 4]) = v1;
            }
        }
    }
}

// ---------------------------------------------------------------------------
extern "C" void kernel_launch(void* const* d_in, const int* in_sizes, int n_in,
                              void* d_out, int out_size)
{
    const float* traj = (const float*)d_in[0];  // (4,16,32,2)
    const float* lat  = (const float*)d_in[1];  // (181,)
    const float* lon  = (const float*)d_in[2];  // (360,)
    float* out = (float*)d_out;                 // (64,181,360) f32

    traj_fused_kernel<<<BT_ * CLUSTER, NTHREADS>>>(traj, lat, lon, out);
}